// round 14
// baseline (speedup 1.0000x reference)
#include <cuda_runtime.h>
#include <cuda_bf16.h>
#include <cstdint>

// ------------------------------------------------------------------ sizes
#define NROWS 8192
#define DDIM  512

// ------------------------------------------------------------ device scratch
__device__ __nv_bfloat16 g_Hb [(size_t)NROWS * DDIM];   // H bf16 row-major
__device__ __nv_bfloat16 g_HbT[(size_t)DDIM * NROWS];   // H^T bf16 [512][8192]
__device__ __nv_bfloat16 g_WqT[(size_t)DDIM * DDIM];    // Wq^T bf16
__device__ __nv_bfloat16 g_WkT[(size_t)DDIM * DDIM];
__device__ __nv_bfloat16 g_Qb [(size_t)NROWS * DDIM];
__device__ __nv_bfloat16 g_Kb [(size_t)NROWS * DDIM];
__device__ __nv_bfloat16 g_P  [(size_t)NROWS * NROWS];  // 128 MB exp(scores)
__device__ float         g_rowsum[NROWS];

// ------------------------------------------------------------ PTX helpers
__device__ __forceinline__ uint32_t smem_u32(const void* p) {
    uint32_t a;
    asm("{ .reg .u64 t; cvta.to.shared.u64 t, %1; cvt.u32.u64 %0, t; }"
        : "=r"(a) : "l"(p));
    return a;
}
__device__ __forceinline__ void cp_async16(uint32_t dst, const void* src) {
    asm volatile("cp.async.cg.shared.global [%0], [%1], 16;"
                 :: "r"(dst), "l"(src) : "memory");
}
__device__ __forceinline__ void cp_commit() {
    asm volatile("cp.async.commit_group;" ::: "memory");
}
template<int N> __device__ __forceinline__ void cp_wait() {
    asm volatile("cp.async.wait_group %0;" :: "n"(N) : "memory");
}
__device__ __forceinline__ void ldsm_x4(uint32_t& r0, uint32_t& r1,
                                        uint32_t& r2, uint32_t& r3, uint32_t addr) {
    asm volatile("ldmatrix.sync.aligned.m8n8.x4.shared.b16 {%0,%1,%2,%3}, [%4];"
                 : "=r"(r0), "=r"(r1), "=r"(r2), "=r"(r3) : "r"(addr));
}
__device__ __forceinline__ void mma16816(float* c, const uint32_t* a,
                                         uint32_t b0, uint32_t b1) {
    asm volatile(
        "mma.sync.aligned.m16n8k16.row.col.f32.bf16.bf16.f32 "
        "{%0,%1,%2,%3}, {%4,%5,%6,%7}, {%8,%9}, {%0,%1,%2,%3};"
        : "+f"(c[0]), "+f"(c[1]), "+f"(c[2]), "+f"(c[3])
        : "r"(a[0]), "r"(a[1]), "r"(a[2]), "r"(a[3]), "r"(b0), "r"(b1));
}
// XOR-swizzled smem addr: 64 bf16 per row (128B), 16B granularity
__device__ __forceinline__ uint32_t sw(uint32_t base, int row, int c16) {
    return base + row * 128 + (((uint32_t)c16 ^ (row & 7)) << 4);
}

// ------------------------------------------------------------ prep kernels
// Wq and Wk fp32 [512][512] -> bf16 transposed, one launch (z selects)
__global__ __launch_bounds__(256) void wt_kernel(
    const float* __restrict__ Wq, const float* __restrict__ Wk)
{
    __shared__ float tile[32][33];
    const float* in = blockIdx.z ? Wk : Wq;
    __nv_bfloat16* out = blockIdx.z ? g_WkT : g_WqT;
    int bx = blockIdx.x * 32, by = blockIdx.y * 32;
    int tx = threadIdx.x, ty = threadIdx.y;
#pragma unroll
    for (int i = 0; i < 32; i += 8)
        tile[ty + i][tx] = in[(size_t)(by + ty + i) * DDIM + bx + tx];
    __syncthreads();
#pragma unroll
    for (int i = 0; i < 32; i += 8)
        out[(size_t)(bx + ty + i) * DDIM + by + tx] = __float2bfloat16(tile[tx][ty + i]);
}

// H fp32 [R][C] -> g_HbT bf16 [C][R] AND g_Hb bf16 [R][C]; also zeros rowsums
__global__ __launch_bounds__(256) void h_prep_kernel(const float* __restrict__ in) {
    __shared__ float tile[32][33];
    int bx = blockIdx.x * 32, by = blockIdx.y * 32;
    int tx = threadIdx.x, ty = threadIdx.y;
    int bid = blockIdx.y * gridDim.x + blockIdx.x;
    if (bid < 32) g_rowsum[bid * 256 + ty * 32 + tx] = 0.0f;
#pragma unroll
    for (int i = 0; i < 32; i += 8) {
        float v = in[(size_t)(by + ty + i) * DDIM + bx + tx];
        tile[ty + i][tx] = v;
        g_Hb[(size_t)(by + ty + i) * DDIM + bx + tx] = __float2bfloat16(v);
    }
    __syncthreads();
#pragma unroll
    for (int i = 0; i < 32; i += 8)
        g_HbT[(size_t)(bx + ty + i) * NROWS + by + tx] =
            __float2bfloat16(tile[tx][ty + i]);
}

// ============================================================ shared MMA step
// one K16-step of the warp-tile MMA (32x64): 2 a-ldsm, 4 b-ldsm, 16 mma
__device__ __forceinline__ void warp_mma_step(
    uint32_t sA, uint32_t sB, int m0, int n0, int lane, int k16,
    float acc[2][8][4])
{
    uint32_t a[2][4];
#pragma unroll
    for (int i = 0; i < 2; ++i) {
        int row = m0 + i * 16 + (lane & 15);
        ldsm_x4(a[i][0], a[i][1], a[i][2], a[i][3],
                sw(sA, row, k16 + (lane >> 4)));
    }
    uint32_t b[4][4];
#pragma unroll
    for (int g = 0; g < 4; ++g) {
        int row = n0 + g * 16 + (lane & 7) + ((lane >> 4) << 3);
        ldsm_x4(b[g][0], b[g][1], b[g][2], b[g][3],
                sw(sB, row, k16 + ((lane >> 3) & 1)));
    }
#pragma unroll
    for (int i = 0; i < 2; ++i)
#pragma unroll
        for (int j = 0; j < 8; ++j)
            mma16816(acc[i][j], a[i], b[j >> 1][(j & 1) * 2],
                     b[j >> 1][(j & 1) * 2 + 1]);
}

// ============================================================ proj GEMM
// D = A @ B^T. CTA tile 128x256, 512 threads (16 warps, 4M x 4N),
// warp tile 32x64. K-chunk 128 (two 64-wide subchunks), 2-stage pipeline.
// out bf16 = D + bias (z selects Q/K)
#define SUB_SZ 49152            // A 16KB + B 32KB per 64-wide subchunk
#define STG2   (2 * SUB_SZ)     // 98304 per K128 chunk
#define SMEM2  (2 * STG2)       // 196608

__device__ __forceinline__ void load_sub(
    const __nv_bfloat16* __restrict__ A, int lda,
    const __nv_bfloat16* __restrict__ B, int ldb,
    int arow0, int brow0, int kbase, uint32_t subaddr)
{
    int t = threadIdx.x;
#pragma unroll
    for (int i = 0; i < 2; ++i) {       // A: 128 rows x 8 c16
        int gid = i * 512 + t;
        int row = gid >> 3, c16 = gid & 7;
        cp_async16(sw(subaddr, row, c16),
                   A + (size_t)(arow0 + row) * lda + kbase + c16 * 8);
    }
#pragma unroll
    for (int i = 0; i < 4; ++i) {       // B: 256 rows x 8 c16
        int gid = i * 512 + t;
        int row = gid >> 3, c16 = gid & 7;
        cp_async16(sw(subaddr + 16384, row, c16),
                   B + (size_t)(brow0 + row) * ldb + kbase + c16 * 8);
    }
}

__device__ __forceinline__ void load_chunk128(
    const __nv_bfloat16* __restrict__ A, int lda,
    const __nv_bfloat16* __restrict__ B, int ldb,
    int arow0, int brow0, int kbase, uint32_t stage)
{
    load_sub(A, lda, B, ldb, arow0, brow0, kbase,      stage);
    load_sub(A, lda, B, ldb, arow0, brow0, kbase + 64, stage + SUB_SZ);
    cp_commit();
}

__global__ __launch_bounds__(512, 1) void proj_kernel(
    const __nv_bfloat16* __restrict__ A,
    const __nv_bfloat16* __restrict__ Bq, const __nv_bfloat16* __restrict__ Bk,
    void* __restrict__ OutQ, void* __restrict__ OutK,
    const float* __restrict__ AuxQ, const float* __restrict__ AuxK)
{
    extern __shared__ __align__(128) char sm[];
    const uint32_t smb = smem_u32(sm);
    const int t = threadIdx.x, lane = t & 31, wid = t >> 5;
    const int wm = wid & 3, wn = wid >> 2;        // 4 x 4 warp grid
    const int bn = blockIdx.x, bm = blockIdx.y;
    const int m0 = wm * 32, n0 = wn * 64;

    const __nv_bfloat16* B = blockIdx.z ? Bk : Bq;
    void* Out              = blockIdx.z ? OutK : OutQ;
    const float* Aux       = blockIdx.z ? AuxK : AuxQ;

    float acc[2][8][4] = {};

    load_chunk128(A, DDIM, B, DDIM, bm * 128, bn * 256, 0, smb);

    for (int c = 0; c < 4; ++c) {
        cp_wait<0>();
        __syncthreads();
        if (c + 1 < 4)
            load_chunk128(A, DDIM, B, DDIM, bm * 128, bn * 256,
                          (c + 1) * 128, smb + ((c + 1) & 1) * STG2);
        const uint32_t st = smb + (c & 1) * STG2;
#pragma unroll
        for (int sub = 0; sub < 2; ++sub) {
            const uint32_t sA = st + sub * SUB_SZ;
            const uint32_t sB = sA + 16384;
#pragma unroll
            for (int ks = 0; ks < 4; ++ks)
                warp_mma_step(sA, sB, m0, n0, lane, ks * 2, acc);
        }
    }

    const int rq = lane >> 2, cq = (lane & 3) * 2;
    __nv_bfloat16* O = (__nv_bfloat16*)Out;
#pragma unroll
    for (int i = 0; i < 2; ++i) {
        int gr0 = bm * 128 + m0 + i * 16 + rq;
#pragma unroll
        for (int j = 0; j < 8; ++j) {
            int gc = bn * 256 + n0 + j * 8 + cq;
            float2 bv = *(const float2*)(Aux + gc);
            __nv_bfloat162 h0 = __floats2bfloat162_rn(acc[i][j][0] + bv.x,
                                                      acc[i][j][1] + bv.y);
            __nv_bfloat162 h1 = __floats2bfloat162_rn(acc[i][j][2] + bv.x,
                                                      acc[i][j][3] + bv.y);
            *(__nv_bfloat162*)(O + (size_t)gr0 * DDIM + gc)       = h0;
            *(__nv_bfloat162*)(O + (size_t)(gr0 + 8) * DDIM + gc) = h1;
        }
    }
}

// ============================================================ scores kernel
// CTA tile 128x128, 256 threads (8 warps, 4M x 2N), warp tile 32x64,
// 2-stage k64 pipeline, 64 KB smem -> 2 CTAs/SM. Grid (64, 64).
#define SCC_STG  32768                 // Q 16KB + K 16KB
#define SCC_SMEM (2 * SCC_STG)         // 65536

__device__ __forceinline__ void scc_load(int bm, int bn, int c, uint32_t stage) {
    int t = threadIdx.x;
#pragma unroll
    for (int i = 0; i < 4; ++i) {       // Q: 128 rows x 8 c16
        int gid = i * 256 + t;
        int row = gid >> 3, c16 = gid & 7;
        cp_async16(sw(stage, row, c16),
                   g_Qb + (size_t)(bm * 128 + row) * DDIM + c * 64 + c16 * 8);
    }
#pragma unroll
    for (int i = 0; i < 4; ++i) {       // K: 128 rows x 8 c16
        int gid = i * 256 + t;
        int row = gid >> 3, c16 = gid & 7;
        cp_async16(sw(stage + 16384, row, c16),
                   g_Kb + (size_t)(bn * 128 + row) * DDIM + c * 64 + c16 * 8);
    }
    cp_commit();
}

__global__ __launch_bounds__(256, 2) void scores_kernel() {
    extern __shared__ __align__(128) char sm[];
    __shared__ float srow[128];
    const uint32_t smb = smem_u32(sm);
    const int t = threadIdx.x, lane = t & 31, wid = t >> 5;
    const int wm = wid & 3, wn = wid >> 2;       // 4 x 2 warp grid
    const int m0 = wm * 32, n0 = wn * 64;
    const int bm = blockIdx.y, bn = blockIdx.x;

    if (t < 128) srow[t] = 0.0f;

    float acc[2][8][4] = {};

    scc_load(bm, bn, 0, smb);

    for (int c = 0; c < 8; ++c) {
        cp_wait<0>();
        __syncthreads();
        if (c + 1 < 8)
            scc_load(bm, bn, c + 1, smb + ((c + 1) & 1) * SCC_STG);
        const uint32_t sA = smb + (c & 1) * SCC_STG;
        const uint32_t sB = sA + 16384;
#pragma unroll
        for (int ks = 0; ks < 4; ++ks)
            warp_mma_step(sA, sB, m0, n0, lane, ks * 2, acc);
    }

    // epilogue: P = exp(D/sqrt(512)) (diag -> 1), bf16 store + rowsum
    const float S2 = 0.06375871566969395f;   // log2(e)/sqrt(512)
    const int rq = lane >> 2, cq = (lane & 3) * 2;
    const bool hasDiag = (bn == bm);
    float rs[2][2] = {};
#pragma unroll
    for (int i = 0; i < 2; ++i) {
        int gr0 = bm * 128 + m0 + i * 16 + rq;
#pragma unroll
        for (int j = 0; j < 8; ++j) {
            int gc = bn * 128 + n0 + j * 8 + cq;
            float p0 = exp2f(acc[i][j][0] * S2);
            float p1 = exp2f(acc[i][j][1] * S2);
            float p2 = exp2f(acc[i][j][2] * S2);
            float p3 = exp2f(acc[i][j][3] * S2);
            if (hasDiag) {   // diag zeroed pre-softmax -> exp(0)=1
                if (gr0 == gc)         p0 = 1.0f;
                if (gr0 == gc + 1)     p1 = 1.0f;
                if (gr0 + 8 == gc)     p2 = 1.0f;
                if (gr0 + 8 == gc + 1) p3 = 1.0f;
            }
            rs[i][0] += p0 + p1;
            rs[i][1] += p2 + p3;
            __nv_bfloat162 h0 = __floats2bfloat162_rn(p0, p1);
            __nv_bfloat162 h1 = __floats2bfloat162_rn(p2, p3);
            *(__nv_bfloat162*)(g_P + (size_t)gr0 * NROWS + gc)       = h0;
            *(__nv_bfloat162*)(g_P + (size_t)(gr0 + 8) * NROWS + gc) = h1;
        }
    }
#pragma unroll
    for (int i = 0; i < 2; ++i)
#pragma unroll
        for (int h = 0; h < 2; ++h) {
            float v = rs[i][h];
            v += __shfl_xor_sync(0xffffffffu, v, 1);
            v += __shfl_xor_sync(0xffffffffu, v, 2);
            if ((lane & 3) == 0)
                atomicAdd(&srow[m0 + i * 16 + h * 8 + rq], v);
        }
    __syncthreads();
    if (t < 128) atomicAdd(&g_rowsum[bm * 128 + t], srow[t]);
}

// ============================================================ out kernel
// O = (P @ H)/rowsum + H.  CTA tile 64x256, 256 threads (8 warps, 2M x 4N),
// warp tile 32x64, 2-stage k64 (40 KB/stage) -> 2 CTAs/SM.
// Grid (2, 128) = 256 CTAs. N-tile stays 256 so P is read exactly 2x.
#define OUT_STG  40960                 // A 8KB + B 32KB
#define OUT_SMEM (2 * OUT_STG)         // 81920

__device__ __forceinline__ void out_load(int bm, int bn, int c, uint32_t stage) {
    int t = threadIdx.x;
#pragma unroll
    for (int i = 0; i < 2; ++i) {       // A = P: 64 rows x 8 c16
        int gid = i * 256 + t;
        int row = gid >> 3, c16 = gid & 7;
        cp_async16(sw(stage, row, c16),
                   g_P + (size_t)(bm * 64 + row) * NROWS + c * 64 + c16 * 8);
    }
#pragma unroll
    for (int i = 0; i < 8; ++i) {       // B = HbT: 256 rows x 8 c16
        int gid = i * 256 + t;
        int row = gid >> 3, c16 = gid & 7;
        cp_async16(sw(stage + 8192, row, c16),
                   g_HbT + (size_t)(bn * 256 + row) * NROWS + c * 64 + c16 * 8);
    }
    cp_commit();
}

__global__ __launch_bounds__(256, 2) void out_kernel(
    const float* __restrict__ H, float* __restrict__ O)
{
    extern __shared__ __align__(128) char sm[];
    const uint32_t smb = smem_u32(sm);
    const int t = threadIdx.x, lane = t & 31, wid = t >> 5;
    const int wm = wid & 1, wn = wid >> 1;       // 2 x 4 warp grid
    const int m0 = wm * 32, n0 = wn * 64;
    const int bm = blockIdx.y, bn = blockIdx.x;

    float acc[2][8][4] = {};

    out_load(bm, bn, 0, smb);

    for (int c = 0; c < 128; ++c) {
        cp_wait<0>();
        __syncthreads();
        if (c + 1 < 128)
            out_load(bm, bn, c + 1, smb + ((c + 1) & 1) * OUT_STG);
        const uint32_t sA = smb + (c & 1) * OUT_STG;
        const uint32_t sB = sA + 8192;
#pragma unroll
        for (int ks = 0; ks < 4; ++ks)
            warp_mma_step(sA, sB, m0, n0, lane, ks * 2, acc);
    }

    const int rq = lane >> 2, cq = (lane & 3) * 2;
#pragma unroll
    for (int i = 0; i < 2; ++i) {
        int gr0 = bm * 64 + m0 + i * 16 + rq;
        float rinv0 = 1.0f / __ldg(&g_rowsum[gr0]);
        float rinv1 = 1.0f / __ldg(&g_rowsum[gr0 + 8]);
        const float* H0 = H + (size_t)gr0 * DDIM;
        const float* H1 = H + (size_t)(gr0 + 8) * DDIM;
#pragma unroll
        for (int j = 0; j < 8; ++j) {
            int gc = bn * 256 + n0 + j * 8 + cq;
            float2 h0 = *(const float2*)(H0 + gc);
            float2 h1 = *(const float2*)(H1 + gc);
            float2 o0 = { acc[i][j][0] * rinv0 + h0.x,
                          acc[i][j][1] * rinv0 + h0.y };
            float2 o1 = { acc[i][j][2] * rinv1 + h1.x,
                          acc[i][j][3] * rinv1 + h1.y };
            *(float2*)(O + (size_t)gr0 * DDIM + gc)       = o0;
            *(float2*)(O + (size_t)(gr0 + 8) * DDIM + gc) = o1;
        }
    }
}

// ------------------------------------------------------------ launch
extern "C" void kernel_launch(void* const* d_in, const int* in_sizes, int n_in,
                              void* d_out, int out_size) {
    const float* H  = (const float*)d_in[0];
    const float* Wq = (const float*)d_in[1];
    const float* bq = (const float*)d_in[2];
    const float* Wk = (const float*)d_in[3];
    const float* bk = (const float*)d_in[4];
    float* out = (float*)d_out;

    void *pHb, *pWqT, *pWkT, *pQb, *pKb;
    cudaGetSymbolAddress(&pHb,  g_Hb);
    cudaGetSymbolAddress(&pWqT, g_WqT);
    cudaGetSymbolAddress(&pWkT, g_WkT);
    cudaGetSymbolAddress(&pQb,  g_Qb);
    cudaGetSymbolAddress(&pKb,  g_Kb);

    cudaFuncSetAttribute(proj_kernel,
        cudaFuncAttributeMaxDynamicSharedMemorySize, SMEM2);
    cudaFuncSetAttribute(scores_kernel,
        cudaFuncAttributeMaxDynamicSharedMemorySize, SCC_SMEM);
    cudaFuncSetAttribute(out_kernel,
        cudaFuncAttributeMaxDynamicSharedMemorySize, OUT_SMEM);

    // launch 1: both W transposes
    wt_kernel<<<dim3(DDIM / 32, DDIM / 32, 2), dim3(32, 8)>>>(Wq, Wk);
    // launch 2: H -> bf16 + H^T, rowsums zeroed
    h_prep_kernel<<<dim3(DDIM / 32, NROWS / 32), dim3(32, 8)>>>(H);
    // launch 3: projections (Q and K via z)
    proj_kernel<<<dim3(2, 64, 2), 512, SMEM2>>>(
        (const __nv_bfloat16*)pHb,
        (const __nv_bfloat16*)pWqT, (const __nv_bfloat16*)pWkT,
        pQb, pKb, bq, bk);
    // launch 4: scores, 2 CTAs/SM
    scores_kernel<<<dim3(64, 64), 256, SCC_SMEM>>>();
    // launch 5 (ncu would need slot 4; profile via dur): out, 64x256 tiles,
    // 2 CTAs/SM, grid (2, 128)
    out_kernel<<<dim3(2, 128), 256, OUT_SMEM>>>(H, out);
}

// round 15
// speedup vs baseline: 1.0331x; 1.0331x over previous
#include <cuda_runtime.h>
#include <cuda_bf16.h>
#include <cstdint>

// ------------------------------------------------------------------ sizes
#define NROWS 8192
#define DDIM  512

// ------------------------------------------------------------ device scratch
__device__ __nv_bfloat16 g_Hb [(size_t)NROWS * DDIM];   // H bf16 row-major
__device__ __nv_bfloat16 g_HbT[(size_t)DDIM * NROWS];   // H^T bf16 [512][8192]
__device__ __nv_bfloat16 g_WqT[(size_t)DDIM * DDIM];    // Wq^T bf16
__device__ __nv_bfloat16 g_WkT[(size_t)DDIM * DDIM];
__device__ __nv_bfloat16 g_Qb [(size_t)NROWS * DDIM];
__device__ __nv_bfloat16 g_Kb [(size_t)NROWS * DDIM];
__device__ __nv_bfloat16 g_P  [(size_t)NROWS * NROWS];  // 128 MB exp(scores)
__device__ float         g_rowsum[NROWS];

// ------------------------------------------------------------ PTX helpers
__device__ __forceinline__ uint32_t smem_u32(const void* p) {
    uint32_t a;
    asm("{ .reg .u64 t; cvta.to.shared.u64 t, %1; cvt.u32.u64 %0, t; }"
        : "=r"(a) : "l"(p));
    return a;
}
__device__ __forceinline__ void cp_async16(uint32_t dst, const void* src) {
    asm volatile("cp.async.cg.shared.global [%0], [%1], 16;"
                 :: "r"(dst), "l"(src) : "memory");
}
__device__ __forceinline__ void cp_commit() {
    asm volatile("cp.async.commit_group;" ::: "memory");
}
template<int N> __device__ __forceinline__ void cp_wait() {
    asm volatile("cp.async.wait_group %0;" :: "n"(N) : "memory");
}
__device__ __forceinline__ void ldsm_x4(uint32_t& r0, uint32_t& r1,
                                        uint32_t& r2, uint32_t& r3, uint32_t addr) {
    asm volatile("ldmatrix.sync.aligned.m8n8.x4.shared.b16 {%0,%1,%2,%3}, [%4];"
                 : "=r"(r0), "=r"(r1), "=r"(r2), "=r"(r3) : "r"(addr));
}
__device__ __forceinline__ void mma16816(float* c, const uint32_t* a,
                                         uint32_t b0, uint32_t b1) {
    asm volatile(
        "mma.sync.aligned.m16n8k16.row.col.f32.bf16.bf16.f32 "
        "{%0,%1,%2,%3}, {%4,%5,%6,%7}, {%8,%9}, {%0,%1,%2,%3};"
        : "+f"(c[0]), "+f"(c[1]), "+f"(c[2]), "+f"(c[3])
        : "r"(a[0]), "r"(a[1]), "r"(a[2]), "r"(a[3]), "r"(b0), "r"(b1));
}
// hardware exp2: single MUFU.EX2, ~2 ulp (negligible vs bf16 quantization)
__device__ __forceinline__ float ex2(float x) {
    float y;
    asm("ex2.approx.f32 %0, %1;" : "=f"(y) : "f"(x));
    return y;
}
// XOR-swizzled smem addr: 64 bf16 per row (128B), 16B granularity
__device__ __forceinline__ uint32_t sw(uint32_t base, int row, int c16) {
    return base + row * 128 + (((uint32_t)c16 ^ (row & 7)) << 4);
}

// ------------------------------------------------------------ prep kernels
// Wq and Wk fp32 [512][512] -> bf16 transposed, one launch (z selects)
__global__ __launch_bounds__(256) void wt_kernel(
    const float* __restrict__ Wq, const float* __restrict__ Wk)
{
    __shared__ float tile[32][33];
    const float* in = blockIdx.z ? Wk : Wq;
    __nv_bfloat16* out = blockIdx.z ? g_WkT : g_WqT;
    int bx = blockIdx.x * 32, by = blockIdx.y * 32;
    int tx = threadIdx.x, ty = threadIdx.y;
#pragma unroll
    for (int i = 0; i < 32; i += 8)
        tile[ty + i][tx] = in[(size_t)(by + ty + i) * DDIM + bx + tx];
    __syncthreads();
#pragma unroll
    for (int i = 0; i < 32; i += 8)
        out[(size_t)(bx + ty + i) * DDIM + by + tx] = __float2bfloat16(tile[tx][ty + i]);
}

// H fp32 [R][C] -> g_HbT bf16 [C][R] AND g_Hb bf16 [R][C]; also zeros rowsums
__global__ __launch_bounds__(256) void h_prep_kernel(const float* __restrict__ in) {
    __shared__ float tile[32][33];
    int bx = blockIdx.x * 32, by = blockIdx.y * 32;
    int tx = threadIdx.x, ty = threadIdx.y;
    int bid = blockIdx.y * gridDim.x + blockIdx.x;
    if (bid < 32) g_rowsum[bid * 256 + ty * 32 + tx] = 0.0f;
#pragma unroll
    for (int i = 0; i < 32; i += 8) {
        float v = in[(size_t)(by + ty + i) * DDIM + bx + tx];
        tile[ty + i][tx] = v;
        g_Hb[(size_t)(by + ty + i) * DDIM + bx + tx] = __float2bfloat16(v);
    }
    __syncthreads();
#pragma unroll
    for (int i = 0; i < 32; i += 8)
        g_HbT[(size_t)(bx + ty + i) * NROWS + by + tx] =
            __float2bfloat16(tile[tx][ty + i]);
}

// ============================================================ shared MMA step
// one K16-step of the warp-tile MMA (32x64): 2 a-ldsm, 4 b-ldsm, 16 mma
__device__ __forceinline__ void warp_mma_step(
    uint32_t sA, uint32_t sB, int m0, int n0, int lane, int k16,
    float acc[2][8][4])
{
    uint32_t a[2][4];
#pragma unroll
    for (int i = 0; i < 2; ++i) {
        int row = m0 + i * 16 + (lane & 15);
        ldsm_x4(a[i][0], a[i][1], a[i][2], a[i][3],
                sw(sA, row, k16 + (lane >> 4)));
    }
    uint32_t b[4][4];
#pragma unroll
    for (int g = 0; g < 4; ++g) {
        int row = n0 + g * 16 + (lane & 7) + ((lane >> 4) << 3);
        ldsm_x4(b[g][0], b[g][1], b[g][2], b[g][3],
                sw(sB, row, k16 + ((lane >> 3) & 1)));
    }
#pragma unroll
    for (int i = 0; i < 2; ++i)
#pragma unroll
        for (int j = 0; j < 8; ++j)
            mma16816(acc[i][j], a[i], b[j >> 1][(j & 1) * 2],
                     b[j >> 1][(j & 1) * 2 + 1]);
}

// ============================================================ generic GEMM
// D = A @ B^T. CTA tile 128x256, 512 threads (16 warps, 4M x 4N),
// warp tile 32x64. K-chunk 128 (two 64-wide subchunks), 2-stage pipeline.
// MODE 0: proj, out bf16 = D + bias (z selects Q/K)
// MODE 2: out fp32 = D / rowsum + H
#define SUB_SZ 49152            // A 16KB + B 32KB per 64-wide subchunk
#define STG2   (2 * SUB_SZ)     // 98304 per K128 chunk
#define SMEM2  (2 * STG2)       // 196608

__device__ __forceinline__ void load_sub(
    const __nv_bfloat16* __restrict__ A, int lda,
    const __nv_bfloat16* __restrict__ B, int ldb,
    int arow0, int brow0, int kbase, uint32_t subaddr)
{
    int t = threadIdx.x;
#pragma unroll
    for (int i = 0; i < 2; ++i) {       // A: 128 rows x 8 c16
        int gid = i * 512 + t;
        int row = gid >> 3, c16 = gid & 7;
        cp_async16(sw(subaddr, row, c16),
                   A + (size_t)(arow0 + row) * lda + kbase + c16 * 8);
    }
#pragma unroll
    for (int i = 0; i < 4; ++i) {       // B: 256 rows x 8 c16
        int gid = i * 512 + t;
        int row = gid >> 3, c16 = gid & 7;
        cp_async16(sw(subaddr + 16384, row, c16),
                   B + (size_t)(brow0 + row) * ldb + kbase + c16 * 8);
    }
}

__device__ __forceinline__ void load_chunk128(
    const __nv_bfloat16* __restrict__ A, int lda,
    const __nv_bfloat16* __restrict__ B, int ldb,
    int arow0, int brow0, int kbase, uint32_t stage)
{
    load_sub(A, lda, B, ldb, arow0, brow0, kbase,      stage);
    load_sub(A, lda, B, ldb, arow0, brow0, kbase + 64, stage + SUB_SZ);
    cp_commit();
}

template<int KC2, int MODE>
__global__ __launch_bounds__(512, 1) void gemm_kernel(
    const __nv_bfloat16* __restrict__ A, int lda,
    const __nv_bfloat16* __restrict__ Bq, const __nv_bfloat16* __restrict__ Bk,
    int ldb, void* __restrict__ OutQ, void* __restrict__ OutK,
    const float* __restrict__ AuxQ, const float* __restrict__ AuxK)
{
    extern __shared__ __align__(128) char sm[];
    const uint32_t smb = smem_u32(sm);
    const int t = threadIdx.x, lane = t & 31, wid = t >> 5;
    const int wm = wid & 3, wn = wid >> 2;        // 4 x 4 warp grid
    const int bn = blockIdx.x, bm = blockIdx.y;
    const int m0 = wm * 32, n0 = wn * 64;

    const __nv_bfloat16* B = (MODE == 0 && blockIdx.z) ? Bk : Bq;
    void* Out              = (MODE == 0 && blockIdx.z) ? OutK : OutQ;
    const float* Aux       = (MODE == 0 && blockIdx.z) ? AuxK : AuxQ;

    float acc[2][8][4] = {};

    load_chunk128(A, lda, B, ldb, bm * 128, bn * 256, 0, smb);

    for (int c = 0; c < KC2; ++c) {
        cp_wait<0>();
        __syncthreads();
        if (c + 1 < KC2)
            load_chunk128(A, lda, B, ldb, bm * 128, bn * 256,
                          (c + 1) * 128, smb + ((c + 1) & 1) * STG2);
        const uint32_t st = smb + (c & 1) * STG2;
#pragma unroll
        for (int sub = 0; sub < 2; ++sub) {
            const uint32_t sA = st + sub * SUB_SZ;
            const uint32_t sB = sA + 16384;
#pragma unroll
            for (int ks = 0; ks < 4; ++ks)
                warp_mma_step(sA, sB, m0, n0, lane, ks * 2, acc);
        }
    }

    // ------------------------------------------------------------ epilogue
    const int rq = lane >> 2, cq = (lane & 3) * 2;

    if (MODE == 0) {
        __nv_bfloat16* O = (__nv_bfloat16*)Out;
#pragma unroll
        for (int i = 0; i < 2; ++i) {
            int gr0 = bm * 128 + m0 + i * 16 + rq;
#pragma unroll
            for (int j = 0; j < 8; ++j) {
                int gc = bn * 256 + n0 + j * 8 + cq;
                float2 bv = *(const float2*)(Aux + gc);
                __nv_bfloat162 h0 = __floats2bfloat162_rn(acc[i][j][0] + bv.x,
                                                          acc[i][j][1] + bv.y);
                __nv_bfloat162 h1 = __floats2bfloat162_rn(acc[i][j][2] + bv.x,
                                                          acc[i][j][3] + bv.y);
                *(__nv_bfloat162*)(O + (size_t)gr0 * DDIM + gc)       = h0;
                *(__nv_bfloat162*)(O + (size_t)(gr0 + 8) * DDIM + gc) = h1;
            }
        }
    } else {   // MODE 2
        float* O = (float*)Out;
#pragma unroll
        for (int i = 0; i < 2; ++i) {
            int gr0 = bm * 128 + m0 + i * 16 + rq;
            float rinv0 = 1.0f / __ldg(&g_rowsum[gr0]);
            float rinv1 = 1.0f / __ldg(&g_rowsum[gr0 + 8]);
            const float* H0 = AuxQ + (size_t)gr0 * DDIM;
            const float* H1 = AuxQ + (size_t)(gr0 + 8) * DDIM;
#pragma unroll
            for (int j = 0; j < 8; ++j) {
                int gc = bn * 256 + n0 + j * 8 + cq;
                float2 h0 = *(const float2*)(H0 + gc);
                float2 h1 = *(const float2*)(H1 + gc);
                float2 o0 = { acc[i][j][0] * rinv0 + h0.x,
                              acc[i][j][1] * rinv0 + h0.y };
                float2 o1 = { acc[i][j][2] * rinv1 + h1.x,
                              acc[i][j][3] * rinv1 + h1.y };
                *(float2*)(O + (size_t)gr0 * DDIM + gc)       = o0;
                *(float2*)(O + (size_t)(gr0 + 8) * DDIM + gc) = o1;
            }
        }
    }
}

// ============================================================ scores kernel
// CTA tile 128x128, 256 threads (8 warps, 4M x 2N), warp tile 32x64,
// 2-stage k64 pipeline, 64 KB smem -> 2 CTAs/SM. Grid (64, 64).
#define SCC_STG  32768                 // Q 16KB + K 16KB
#define SCC_SMEM (2 * SCC_STG)         // 65536

__device__ __forceinline__ void scc_load(int bm, int bn, int c, uint32_t stage) {
    int t = threadIdx.x;
#pragma unroll
    for (int i = 0; i < 4; ++i) {       // Q: 128 rows x 8 c16
        int gid = i * 256 + t;
        int row = gid >> 3, c16 = gid & 7;
        cp_async16(sw(stage, row, c16),
                   g_Qb + (size_t)(bm * 128 + row) * DDIM + c * 64 + c16 * 8);
    }
#pragma unroll
    for (int i = 0; i < 4; ++i) {       // K: 128 rows x 8 c16
        int gid = i * 256 + t;
        int row = gid >> 3, c16 = gid & 7;
        cp_async16(sw(stage + 16384, row, c16),
                   g_Kb + (size_t)(bn * 128 + row) * DDIM + c * 64 + c16 * 8);
    }
    cp_commit();
}

__global__ __launch_bounds__(256, 2) void scores_kernel() {
    extern __shared__ __align__(128) char sm[];
    __shared__ float srow[128];
    const uint32_t smb = smem_u32(sm);
    const int t = threadIdx.x, lane = t & 31, wid = t >> 5;
    const int wm = wid & 3, wn = wid >> 2;       // 4 x 2 warp grid
    const int m0 = wm * 32, n0 = wn * 64;
    const int bm = blockIdx.y, bn = blockIdx.x;

    if (t < 128) srow[t] = 0.0f;

    float acc[2][8][4] = {};

    scc_load(bm, bn, 0, smb);

    for (int c = 0; c < 8; ++c) {
        cp_wait<0>();
        __syncthreads();
        if (c + 1 < 8)
            scc_load(bm, bn, c + 1, smb + ((c + 1) & 1) * SCC_STG);
        const uint32_t sA = smb + (c & 1) * SCC_STG;
        const uint32_t sB = sA + 16384;
#pragma unroll
        for (int ks = 0; ks < 4; ++ks)
            warp_mma_step(sA, sB, m0, n0, lane, ks * 2, acc);
    }

    // epilogue: P = exp(D/sqrt(512)) (diag -> 1), bf16 store + rowsum.
    // exp via single-MUFU ex2.approx (harness may not enable fast-math).
    const float S2 = 0.06375871566969395f;   // log2(e)/sqrt(512)
    const int rq = lane >> 2, cq = (lane & 3) * 2;
    const bool hasDiag = (bn == bm);
    float rs[2][2] = {};
#pragma unroll
    for (int i = 0; i < 2; ++i) {
        int gr0 = bm * 128 + m0 + i * 16 + rq;
#pragma unroll
        for (int j = 0; j < 8; ++j) {
            int gc = bn * 128 + n0 + j * 8 + cq;
            float p0 = ex2(acc[i][j][0] * S2);
            float p1 = ex2(acc[i][j][1] * S2);
            float p2 = ex2(acc[i][j][2] * S2);
            float p3 = ex2(acc[i][j][3] * S2);
            if (hasDiag) {   // diag zeroed pre-softmax -> exp(0)=1
                if (gr0 == gc)         p0 = 1.0f;
                if (gr0 == gc + 1)     p1 = 1.0f;
                if (gr0 + 8 == gc)     p2 = 1.0f;
                if (gr0 + 8 == gc + 1) p3 = 1.0f;
            }
            rs[i][0] += p0 + p1;
            rs[i][1] += p2 + p3;
            __nv_bfloat162 h0 = __floats2bfloat162_rn(p0, p1);
            __nv_bfloat162 h1 = __floats2bfloat162_rn(p2, p3);
            *(__nv_bfloat162*)(g_P + (size_t)gr0 * NROWS + gc)       = h0;
            *(__nv_bfloat162*)(g_P + (size_t)(gr0 + 8) * NROWS + gc) = h1;
        }
    }
#pragma unroll
    for (int i = 0; i < 2; ++i)
#pragma unroll
        for (int h = 0; h < 2; ++h) {
            float v = rs[i][h];
            v += __shfl_xor_sync(0xffffffffu, v, 1);
            v += __shfl_xor_sync(0xffffffffu, v, 2);
            if ((lane & 3) == 0)
                atomicAdd(&srow[m0 + i * 16 + h * 8 + rq], v);
        }
    __syncthreads();
    if (t < 128) atomicAdd(&g_rowsum[bm * 128 + t], srow[t]);
}

// ------------------------------------------------------------ launch
extern "C" void kernel_launch(void* const* d_in, const int* in_sizes, int n_in,
                              void* d_out, int out_size) {
    const float* H  = (const float*)d_in[0];
    const float* Wq = (const float*)d_in[1];
    const float* bq = (const float*)d_in[2];
    const float* Wk = (const float*)d_in[3];
    const float* bk = (const float*)d_in[4];
    float* out = (float*)d_out;

    void *pHb, *pHbT, *pWqT, *pWkT, *pQb, *pKb, *pP;
    cudaGetSymbolAddress(&pHb,  g_Hb);
    cudaGetSymbolAddress(&pHbT, g_HbT);
    cudaGetSymbolAddress(&pWqT, g_WqT);
    cudaGetSymbolAddress(&pWkT, g_WkT);
    cudaGetSymbolAddress(&pQb,  g_Qb);
    cudaGetSymbolAddress(&pKb,  g_Kb);
    cudaGetSymbolAddress(&pP,   g_P);

    cudaFuncSetAttribute(gemm_kernel<4, 0>,
        cudaFuncAttributeMaxDynamicSharedMemorySize, SMEM2);
    cudaFuncSetAttribute(gemm_kernel<64, 2>,
        cudaFuncAttributeMaxDynamicSharedMemorySize, SMEM2);
    cudaFuncSetAttribute(scores_kernel,
        cudaFuncAttributeMaxDynamicSharedMemorySize, SCC_SMEM);

    // launch 1: both W transposes
    wt_kernel<<<dim3(DDIM / 32, DDIM / 32, 2), dim3(32, 8)>>>(Wq, Wk);
    // launch 2: H -> bf16 + H^T, rowsums zeroed
    h_prep_kernel<<<dim3(DDIM / 32, NROWS / 32), dim3(32, 8)>>>(H);
    // launch 3: projections (Q and K via z)
    gemm_kernel<4, 0><<<dim3(2, 64, 2), 512, SMEM2>>>(
        (const __nv_bfloat16*)pHb, DDIM,
        (const __nv_bfloat16*)pWqT, (const __nv_bfloat16*)pWkT, DDIM,
        pQb, pKb, bq, bk);
    // launch 4 (ncu slot): scores, 2 CTAs/SM
    scores_kernel<<<dim3(64, 64), 256, SCC_SMEM>>>();
    // launch 5: out = (P H)/rowsum + H  (R12 champion config)
    gemm_kernel<64, 2><<<dim3(2, 64), 512, SMEM2>>>(
        (const __nv_bfloat16*)pP, NROWS,
        (const __nv_bfloat16*)pHbT, nullptr, NROWS,
        out, nullptr, H, nullptr);
}